// round 4
// baseline (speedup 1.0000x reference)
#include <cuda_runtime.h>
#include <cuda_fp16.h>
#include <cstdint>

#define HH 512
#define WW 512
#define BATCH 32
#define WPR 16                       // uint32 words per row (512 bits)
#define WORDS_PER_IMG (HH * WPR)     // 8192 words = 32KB
#define TILE_H 32
#define GRAY_ROWS (TILE_H + 4)       // 36
#define MAG_ROWS  (TILE_H + 2)       // 34
#define MAGP2 258                    // mag pitch in half2 (516 halfs: 2 zero cols each side)
#define HPITCH 17                    // hysteresis exchange pitch (conflict-free)
#define FTHREADS 512

// ---------------- device scratch (no allocations allowed) ----------------
__device__ uint32_t g_weak  [2 * BATCH * WORDS_PER_IMG];
__device__ uint32_t g_strong[2 * BATCH * WORDS_PER_IMG];
__device__ uint32_t g_edges [2 * BATCH * WORDS_PER_IMG];
__device__ unsigned int g_count;
__device__ unsigned int g_done;

__device__ __forceinline__ unsigned spread16(unsigned x) {
    x &= 0xFFFFu;
    x = (x | (x << 8)) & 0x00FF00FFu;
    x = (x | (x << 4)) & 0x0F0F0F0Fu;
    x = (x | (x << 2)) & 0x33333333u;
    x = (x | (x << 1)) & 0x55555555u;
    return x;
}

// gray triple: pairs for cols (c-1,c), (c,c+1), (c+1,c+2) with reflect at 0/510
__device__ __forceinline__ void gtrip(const __half2* row, int c2,
                                      __half2& L, __half2& C, __half2& R) {
    C = row[c2];
    if (c2 > 0) {
        __half2 P = row[c2 - 1];
        L = __halves2half2(__high2half(P), __low2half(C));
    } else L = __lowhigh2highlow(C);
    if (c2 < 255) {
        __half2 N = row[c2 + 1];
        R = __halves2half2(__high2half(C), __low2half(N));
    } else R = __lowhigh2highlow(C);
}

// mag triple: zero-padded, no branches. k0 = c2+1 in pitch-258 row.
__device__ __forceinline__ void mtrip(const __half2* row, int c2,
                                      __half2& L, __half2& C, __half2& R) {
    __half2 P = row[c2], N = row[c2 + 2];
    C = row[c2 + 1];
    L = __halves2half2(__high2half(P), __low2half(C));
    R = __halves2half2(__high2half(C), __low2half(N));
}

// Sobel on half2 triples (all values exact integers -> exact in fp16)
__device__ __forceinline__ void sobel2(__half2 tL, __half2 tC, __half2 tR,
                                       __half2 mL, __half2 mR,
                                       __half2 bL, __half2 bC, __half2 bR,
                                       __half2& gx2, __half2& gy2) {
    const __half2 two2 = __floats2half2_rn(2.0f, 2.0f);
    __half2 dt = __hsub2(tR, tL);
    __half2 dm = __hsub2(mR, mL);
    __half2 db = __hsub2(bR, bL);
    gx2 = __hadd2(__hfma2(two2, dm, dt), db);
    __half2 st = __hfma2(two2, tC, __hadd2(tL, tR));
    __half2 sb = __hfma2(two2, bC, __hadd2(bL, bR));
    gy2 = __hsub2(sb, st);
}

// ---------------- fused gray -> sobel -> NMS -> threshold -> bitpack ------
__global__ __launch_bounds__(FTHREADS) void k_frontend(const float* __restrict__ A,
                                                       const float* __restrict__ B) {
    extern __shared__ __half2 smem2[];
    __half2* sg2 = smem2;                      // [GRAY_ROWS][256]
    __half2* sm2 = smem2 + GRAY_ROWS * 256;    // [MAG_ROWS][MAGP2]

    const int tid  = threadIdx.x;
    const int tile = blockIdx.x;
    const int b    = blockIdx.y;
    const int im   = blockIdx.z;
    const int r0   = tile * TILE_H;
    const float* img = (im == 0 ? A : B) + (size_t)b * 3 * HH * WW;

    if (tile == 0 && b == 0 && im == 0 && tid == 0) { g_count = 0u; g_done = 0u; }

    // Stage 1: quantized grayscale, 2 px/thread, reflect rows (halo 2)
    for (int p = tid; p < GRAY_ROWS * 256; p += FTHREADS) {
        int rr = p >> 8, c2 = p & 255;
        int gr = r0 - 2 + rr;
        gr = gr < 0 ? -gr : (gr > HH - 1 ? 2 * (HH - 1) - gr : gr);
        const float* base = img + gr * WW + 2 * c2;
        float2 r2 = *(const float2*)(base);
        float2 g2 = *(const float2*)(base + HH * WW);
        float2 b2 = *(const float2*)(base + 2 * HH * WW);
        // match XLA: ((0.299*R + 0.587*G) + 0.114*B), each op separately rounded
        float v0 = __fadd_rn(__fadd_rn(__fmul_rn(0.299f, r2.x), __fmul_rn(0.587f, g2.x)),
                             __fmul_rn(0.114f, b2.x));
        float v1 = __fadd_rn(__fadd_rn(__fmul_rn(0.299f, r2.y), __fmul_rn(0.587f, g2.y)),
                             __fmul_rn(0.114f, b2.y));
        v0 = fminf(fmaxf(floorf(__fmul_rn(v0, 255.0f)), 0.0f), 255.0f);
        v1 = fminf(fmaxf(floorf(__fmul_rn(v1, 255.0f)), 0.0f), 255.0f);
        sg2[p] = __floats2half2_rn(v0, v1);    // exact integers 0..255
    }
    __syncthreads();

    // Stage 2: |gx|+|gy| magnitude, 2 px/thread; zero rows outside the image
    for (int p = tid; p < MAG_ROWS * 256; p += FTHREADS) {
        int rr = p >> 8, c2 = p & 255;
        int gr = r0 - 1 + rr;
        __half2 m2 = __floats2half2_rn(0.0f, 0.0f);
        if (gr >= 0 && gr < HH) {
            int sr = rr + 1;
            __half2 tL, tC, tR, mL, mC, mR, bL, bC, bR;
            gtrip(sg2 + (sr - 1) * 256, c2, tL, tC, tR);
            gtrip(sg2 +  sr      * 256, c2, mL, mC, mR);
            gtrip(sg2 + (sr + 1) * 256, c2, bL, bC, bR);
            __half2 gx2, gy2;
            sobel2(tL, tC, tR, mL, mR, bL, bC, bR, gx2, gy2);
            m2 = __hadd2(__habs2(gx2), __habs2(gy2));   // <= 2040, exact
        }
        sm2[rr * MAGP2 + c2 + 1] = m2;
    }
    for (int r = tid; r < MAG_ROWS; r += FTHREADS) {
        sm2[r * MAGP2]       = __floats2half2_rn(0.0f, 0.0f);
        sm2[r * MAGP2 + 257] = __floats2half2_rn(0.0f, 0.0f);
    }
    __syncthreads();

    // Stage 3: NMS + threshold + bitpack; 2 px/thread, warp = 64 cols = 2 words
    const int lane = tid & 31;
    const int wgrp = (tid >> 5) & 7;           // warp's 64-col group within row
    const size_t obase = ((size_t)(im * BATCH + b)) * WORDS_PER_IMG;
    const __half2 h25 = __floats2half2_rn(25.0f, 25.0f);
    const __half2 h76 = __floats2half2_rn(76.0f, 76.0f);
    for (int pt = tid; pt < TILE_H * 256; pt += FTHREADS) {
        int rr = pt >> 8, c2 = pt & 255;       // rr uniform per warp
        int sr = rr + 2;
        __half2 tL, tC, tR, mL, mC, mR, bL, bC, bR;
        gtrip(sg2 + (sr - 1) * 256, c2, tL, tC, tR);
        gtrip(sg2 +  sr      * 256, c2, mL, mC, mR);
        gtrip(sg2 + (sr + 1) * 256, c2, bL, bC, bR);
        __half2 gx2, gy2;
        sobel2(tL, tC, tR, mL, mR, bL, bC, bR, gx2, gy2);
        __half2 mag2 = __hadd2(__habs2(gx2), __habs2(gy2));

        __half2 NW2, N2, NE2, W2, C2u, E2, SW2, S2, SE2;
        mtrip(sm2 +  rr      * MAGP2, c2, NW2, N2, NE2);
        mtrip(sm2 + (rr + 1) * MAGP2, c2, W2, C2u, E2);
        mtrip(sm2 + (rr + 2) * MAGP2, c2, SW2, S2, SE2);

        unsigned kh = __hgt2_mask(mag2, W2)  & __hge2_mask(mag2, E2);
        unsigned kv = __hgt2_mask(mag2, N2)  & __hge2_mask(mag2, S2);
        unsigned k1 = __hgt2_mask(mag2, NW2) & __hge2_mask(mag2, SE2);
        unsigned k2 = __hgt2_mask(mag2, NE2) & __hge2_mask(mag2, SW2);
        unsigned wm = __hgt2_mask(mag2, h25);
        unsigned sm_ = __hgt2_mask(mag2, h76);

        // classification in fp32 (matches reference rounding); values exact ints
        float gx0 = __half2float(__low2half(gx2)),  gx1 = __half2float(__high2half(gx2));
        float gy0 = __half2float(__low2half(gy2)),  gy1 = __half2float(__high2half(gy2));
        float ax0 = fabsf(gx0), ay0 = fabsf(gy0);
        float ax1 = fabsf(gx1), ay1 = fabsf(gy1);
        bool h0 = ay0 <= __fmul_rn((float)0.4142135623730951, ax0);
        bool v0 = ay0 >= __fmul_rn((float)2.414213562373095,  ax0);
        bool s0 = __fmul_rn(gx0, gy0) >= 0.0f;
        bool h1 = ay1 <= __fmul_rn((float)0.4142135623730951, ax1);
        bool v1 = ay1 >= __fmul_rn((float)2.414213562373095,  ax1);
        bool s1 = __fmul_rn(gx1, gy1) >= 0.0f;
        unsigned km0 = h0 ? kh : (v0 ? kv : (s0 ? k1 : k2));
        unsigned km1 = h1 ? kh : (v1 ? kv : (s1 ? k1 : k2));
        bool wk0 = (km0 & wm)  & 0x1u;
        bool st0 = (km0 & sm_) & 0x1u;
        bool wk1 = ((km1 & wm)  >> 16) & 0x1u;
        bool st1 = ((km1 & sm_) >> 16) & 0x1u;

        unsigned we = __ballot_sync(0xffffffffu, wk0);
        unsigned wo = __ballot_sync(0xffffffffu, wk1);
        unsigned se = __ballot_sync(0xffffffffu, st0);
        unsigned so = __ballot_sync(0xffffffffu, st1);
        if (lane < 4) {
            bool is_st = lane >= 2;
            int hi = lane & 1;
            unsigned e = is_st ? se : we;
            unsigned o = is_st ? so : wo;
            if (hi) { e >>= 16; o >>= 16; }
            unsigned wordv = spread16(e) | (spread16(o) << 1);
            uint32_t* dst = is_st ? (g_strong + obase) : (g_weak + obase);
            dst[(size_t)(r0 + rr) * WPR + 2 * wgrp + hi] = wordv;
        }
    }
}

// ---------------- bitwise hysteresis: 1 CTA/image, 1 row/thread, regs-resident
__global__ __launch_bounds__(512) void k_hyster() {
    extern __shared__ uint32_t sbuf[];   // 2 buffers of [512][HPITCH]
    const int t = threadIdx.x;           // row index 0..511
    const int im = blockIdx.x >> 5, b = blockIdx.x & 31;
    const size_t base = ((size_t)(im * BATCH + b)) * WORDS_PER_IMG + (size_t)t * WPR;

    uint32_t w[WPR], s[WPR], c[WPR];
    {
        const uint4* pw = (const uint4*)(g_weak + base);
        const uint4* ps = (const uint4*)(g_strong + base);
#pragma unroll
        for (int q = 0; q < 4; q++) {
            uint4 a = pw[q];
            w[4*q+0]=a.x; w[4*q+1]=a.y; w[4*q+2]=a.z; w[4*q+3]=a.w;
            uint4 d = ps[q];
            s[4*q+0]=d.x; s[4*q+1]=d.y; s[4*q+2]=d.z; s[4*q+3]=d.w;
        }
    }
#pragma unroll
    for (int i = 0; i < WPR; i++) c[i] = s[i];

    uint32_t* b0 = sbuf;
    uint32_t* b1 = sbuf + HH * HPITCH;
#pragma unroll
    for (int i = 0; i < WPR; i++) b0[t * HPITCH + i] = c[i];
    __syncthreads();

    for (int it = 0; it < 64; ++it) {
        const uint32_t* rd = (it & 1) ? b1 : b0;
        uint32_t*       wr = (it & 1) ? b0 : b1;
        const uint32_t* pu = rd + (t - 1) * HPITCH;
        const uint32_t* pd = rd + (t + 1) * HPITCH;
        uint32_t vor[WPR];
#pragma unroll
        for (int i = 0; i < WPR; i++) {
            uint32_t u = (t > 0)      ? pu[i] : 0u;
            uint32_t d = (t < HH - 1) ? pd[i] : 0u;
            vor[i] = u | d | c[i];               // vertical max (separable)
        }
        uint32_t ch = 0u;
#pragma unroll
        for (int i = 0; i < WPR; i++) {
            uint32_t lo = (i > 0)       ? vor[i - 1] : 0u;
            uint32_t hi = (i < WPR - 1) ? vor[i + 1] : 0u;
            uint32_t l = __funnelshift_l(lo, vor[i], 1);   // col-1 values
            uint32_t r = __funnelshift_r(vor[i], hi, 1);   // col+1 values
            uint32_t d3 = l | vor[i] | r;                  // 3x3 dilate done
            uint32_t nv = (d3 & w[i]) | s[i];
            ch |= nv ^ c[i];
            c[i] = nv;
            wr[t * HPITCH + i] = nv;
        }
        int any = __syncthreads_or((int)(ch != 0u));
        if (!any) break;  // fixed point => identical to reference while_loop
    }

    {
        uint4* pe = (uint4*)(g_edges + base);
#pragma unroll
        for (int q = 0; q < 4; q++)
            pe[q] = make_uint4(c[4*q+0], c[4*q+1], c[4*q+2], c[4*q+3]);
    }
}

// ---------------- XOR popcount reduction + sqrt + output -------------------
__global__ __launch_bounds__(256) void k_diff(float* out, int n) {
    const int totalv = (BATCH * WORDS_PER_IMG) / 4;    // uint4 per image-set
    const uint4* ea = (const uint4*)g_edges;
    const uint4* eb = ea + totalv;
    int idx = blockIdx.x * blockDim.x + threadIdx.x;
    int sum = 0;
    for (int i = idx; i < totalv; i += gridDim.x * blockDim.x) {
        uint4 a = ea[i], d = eb[i];
        sum += __popc(a.x ^ d.x) + __popc(a.y ^ d.y)
             + __popc(a.z ^ d.z) + __popc(a.w ^ d.w);
    }
#pragma unroll
    for (int o = 16; o > 0; o >>= 1) sum += __shfl_down_sync(0xffffffffu, sum, o);
    __shared__ int wsum[8];
    int lane = threadIdx.x & 31, wq = threadIdx.x >> 5;
    if (lane == 0) wsum[wq] = sum;
    __syncthreads();
    if (threadIdx.x == 0) {
        int s2 = 0;
#pragma unroll
        for (int i = 0; i < 8; i++) s2 += wsum[i];
        atomicAdd(&g_count, (unsigned)s2);
        __threadfence();
        unsigned ticket = atomicAdd(&g_done, 1u);
        if (ticket == gridDim.x - 1) {          // last block: finalize
            unsigned total = atomicAdd(&g_count, 0u);
            float v = sqrtf((float)total);
            for (int i = 0; i < n; i++) out[i] = v;
        }
    }
}

// ---------------- launch ---------------------------------------------------
extern "C" void kernel_launch(void* const* d_in, const int* in_sizes, int n_in,
                              void* d_out, int out_size) {
    const float* A = (const float*)d_in[0];
    const float* B = (const float*)d_in[1];

    size_t smemF = (size_t)(GRAY_ROWS * 256 + MAG_ROWS * MAGP2) * sizeof(__half2); // ~71.1KB
    size_t smemH = (size_t)2 * HH * HPITCH * sizeof(uint32_t);                     // 69,632B

    cudaFuncSetAttribute(k_frontend, cudaFuncAttributeMaxDynamicSharedMemorySize, (int)smemF);
    cudaFuncSetAttribute(k_hyster,   cudaFuncAttributeMaxDynamicSharedMemorySize, (int)smemH);

    k_frontend<<<dim3(HH / TILE_H, BATCH, 2), FTHREADS, smemF>>>(A, B);
    k_hyster<<<2 * BATCH, 512, smemH>>>();
    k_diff<<<256, 256>>>((float*)d_out, out_size);
}

// round 5
// speedup vs baseline: 1.1078x; 1.1078x over previous
#include <cuda_runtime.h>
#include <cuda_fp16.h>
#include <cstdint>

#define HH 512
#define WW 512
#define BATCH 32
#define WPR 16                       // uint32 words per row (512 bits)
#define WORDS_PER_IMG (HH * WPR)     // 8192 words = 32KB
#define TILE_H 32
#define GRAY_ROWS (TILE_H + 4)       // 36
#define MAG_ROWS  (TILE_H + 2)       // 34
#define MAGP2 258                    // mag pitch in half2 (2 zero half2 pads)
#define HPITCH 17                    // hysteresis exchange pitch (conflict-free)
#define FTHREADS 1024

// ---------------- device scratch (no allocations allowed) ----------------
__device__ uint32_t g_weak  [2 * BATCH * WORDS_PER_IMG];
__device__ uint32_t g_strong[2 * BATCH * WORDS_PER_IMG];
__device__ uint32_t g_edges [2 * BATCH * WORDS_PER_IMG];
__device__ unsigned int g_count;
__device__ unsigned int g_done;

__device__ __forceinline__ unsigned spread16(unsigned x) {
    x &= 0xFFFFu;
    x = (x | (x << 8)) & 0x00FF00FFu;
    x = (x | (x << 4)) & 0x0F0F0F0Fu;
    x = (x | (x << 2)) & 0x33333333u;
    x = (x | (x << 1)) & 0x55555555u;
    return x;
}

// gray triple: pairs for cols (c-1,c), (c,c+1), (c+1,c+2) with reflect at 0/510
__device__ __forceinline__ void gtrip(const __half2* row, int c2,
                                      __half2& L, __half2& C, __half2& R) {
    C = row[c2];
    if (c2 > 0) {
        __half2 P = row[c2 - 1];
        L = __halves2half2(__high2half(P), __low2half(C));
    } else L = __lowhigh2highlow(C);
    if (c2 < 255) {
        __half2 N = row[c2 + 1];
        R = __halves2half2(__high2half(C), __low2half(N));
    } else R = __lowhigh2highlow(C);
}

// mag triple: zero-padded, no branches.
__device__ __forceinline__ void mtrip(const __half2* row, int c2,
                                      __half2& L, __half2& C, __half2& R) {
    __half2 P = row[c2], N = row[c2 + 2];
    C = row[c2 + 1];
    L = __halves2half2(__high2half(P), __low2half(C));
    R = __halves2half2(__high2half(C), __low2half(N));
}

// Sobel on half2 triples (all values exact integers -> exact in fp16)
__device__ __forceinline__ void sobel2(__half2 tL, __half2 tC, __half2 tR,
                                       __half2 mL, __half2 mR,
                                       __half2 bL, __half2 bC, __half2 bR,
                                       __half2& gx2, __half2& gy2) {
    const __half2 two2 = __floats2half2_rn(2.0f, 2.0f);
    __half2 dt = __hsub2(tR, tL);
    __half2 dm = __hsub2(mR, mL);
    __half2 db = __hsub2(bR, bL);
    gx2 = __hadd2(__hfma2(two2, dm, dt), db);
    __half2 st = __hfma2(two2, tC, __hadd2(tL, tR));
    __half2 sb = __hfma2(two2, bC, __hadd2(bL, bR));
    gy2 = __hsub2(sb, st);
}

__device__ __forceinline__ float grayq(float r, float g, float b) {
    // match XLA: ((0.299*R + 0.587*G) + 0.114*B), each op separately rounded
    float v = __fadd_rn(__fadd_rn(__fmul_rn(0.299f, r), __fmul_rn(0.587f, g)),
                        __fmul_rn(0.114f, b));
    return fminf(fmaxf(floorf(__fmul_rn(v, 255.0f)), 0.0f), 255.0f);
}

// ---------------- fused gray -> sobel+class -> NMS -> threshold -> bitpack
__global__ __launch_bounds__(FTHREADS, 2) void k_frontend(const float* __restrict__ A,
                                                          const float* __restrict__ B) {
    extern __shared__ __half2 smem2[];
    __half2* sg2 = smem2;                      // [GRAY_ROWS][256]
    __half2* sm2 = smem2 + GRAY_ROWS * 256;    // [MAG_ROWS][MAGP2]
    uint8_t* sdc = (uint8_t*)(smem2 + GRAY_ROWS * 256 + MAG_ROWS * MAGP2); // [TILE_H][256]

    const int tid  = threadIdx.x;
    const int tile = blockIdx.x;
    const int b    = blockIdx.y;
    const int im   = blockIdx.z;
    const int r0   = tile * TILE_H;
    const float* img = (im == 0 ? A : B) + (size_t)b * 3 * HH * WW;

    if (tile == 0 && b == 0 && im == 0 && tid == 0) { g_count = 0u; g_done = 0u; }

    // Stage 1: quantized grayscale, 4 px/thread via float4, reflect rows (halo 2)
    for (int p = tid; p < GRAY_ROWS * 128; p += FTHREADS) {
        int rr = p >> 7, c4 = p & 127;
        int gr = r0 - 2 + rr;
        gr = gr < 0 ? -gr : (gr > HH - 1 ? 2 * (HH - 1) - gr : gr);
        const float4* base = (const float4*)(img + gr * WW) + c4;
        float4 r4 = base[0];
        float4 g4 = base[(HH * WW) / 4];
        float4 b4 = base[(2 * HH * WW) / 4];
        __half2 h01 = __floats2half2_rn(grayq(r4.x, g4.x, b4.x), grayq(r4.y, g4.y, b4.y));
        __half2 h23 = __floats2half2_rn(grayq(r4.z, g4.z, b4.z), grayq(r4.w, g4.w, b4.w));
        uint2 pk;
        pk.x = *(const unsigned*)&h01;
        pk.y = *(const unsigned*)&h23;
        *reinterpret_cast<uint2*>(&sg2[rr * 256 + 2 * c4]) = pk;
    }
    __syncthreads();

    // Stage 2: magnitude + direction class, 2 px/thread
    for (int p = tid; p < MAG_ROWS * 256; p += FTHREADS) {
        int rr = p >> 8, c2 = p & 255;
        int gr = r0 - 1 + rr;
        __half2 m2 = __floats2half2_rn(0.0f, 0.0f);
        if (gr >= 0 && gr < HH) {
            int sr = rr + 1;
            __half2 tL, tC, tR, mL, mC, mR, bL, bC, bR;
            gtrip(sg2 + (sr - 1) * 256, c2, tL, tC, tR);
            gtrip(sg2 +  sr      * 256, c2, mL, mC, mR);
            gtrip(sg2 + (sr + 1) * 256, c2, bL, bC, bR);
            __half2 gx2, gy2;
            sobel2(tL, tC, tR, mL, mR, bL, bC, bR, gx2, gy2);
            m2 = __hadd2(__habs2(gx2), __habs2(gy2));   // <= 2040, exact
            if (rr >= 1 && rr <= TILE_H) {
                float2 gxf = __half22float2(gx2);
                float2 gyf = __half22float2(gy2);
                float ax0 = fabsf(gxf.x), ay0 = fabsf(gyf.x);
                float ax1 = fabsf(gxf.y), ay1 = fabsf(gyf.y);
                bool h0 = ay0 <= __fmul_rn((float)0.4142135623730951, ax0);
                bool v0 = ay0 >= __fmul_rn((float)2.414213562373095,  ax0);
                bool s0 = __fmul_rn(gxf.x, gyf.x) >= 0.0f;
                bool h1 = ay1 <= __fmul_rn((float)0.4142135623730951, ax1);
                bool v1 = ay1 >= __fmul_rn((float)2.414213562373095,  ax1);
                bool s1 = __fmul_rn(gxf.y, gyf.y) >= 0.0f;
                int cls0 = h0 ? 0 : (v0 ? 1 : (s0 ? 2 : 3));
                int cls1 = h1 ? 0 : (v1 ? 1 : (s1 ? 2 : 3));
                sdc[(rr - 1) * 256 + c2] = (uint8_t)(cls0 | (cls1 << 2));
            }
        }
        sm2[rr * MAGP2 + c2 + 1] = m2;
    }
    for (int r = tid; r < MAG_ROWS; r += FTHREADS) {
        sm2[r * MAGP2]       = __floats2half2_rn(0.0f, 0.0f);
        sm2[r * MAGP2 + 257] = __floats2half2_rn(0.0f, 0.0f);
    }
    __syncthreads();

    // Stage 3: NMS from cached mag+class + threshold + bitpack; 2 px/thread
    const int lane = tid & 31;
    const int wgrp = (tid >> 5) & 7;           // warp's 64-col group within row
    const size_t obase = ((size_t)(im * BATCH + b)) * WORDS_PER_IMG;
    const __half2 h25 = __floats2half2_rn(25.0f, 25.0f);
    const __half2 h76 = __floats2half2_rn(76.0f, 76.0f);
    for (int pt = tid; pt < TILE_H * 256; pt += FTHREADS) {
        int rr = pt >> 8, c2 = pt & 255;       // rr uniform per warp

        __half2 NW2, N2, NE2, W2, C2u, E2, SW2, S2, SE2;
        mtrip(sm2 +  rr      * MAGP2, c2, NW2, N2, NE2);
        mtrip(sm2 + (rr + 1) * MAGP2, c2, W2, C2u, E2);
        mtrip(sm2 + (rr + 2) * MAGP2, c2, SW2, S2, SE2);
        __half2 mag2 = C2u;

        unsigned kh = __hgt2_mask(mag2, W2)  & __hge2_mask(mag2, E2);
        unsigned kv = __hgt2_mask(mag2, N2)  & __hge2_mask(mag2, S2);
        unsigned k1 = __hgt2_mask(mag2, NW2) & __hge2_mask(mag2, SE2);
        unsigned k2 = __hgt2_mask(mag2, NE2) & __hge2_mask(mag2, SW2);
        unsigned wm = __hgt2_mask(mag2, h25);
        unsigned sm_ = __hgt2_mask(mag2, h76);

        int cb = sdc[rr * 256 + c2];
        int cls0 = cb & 3, cls1 = cb >> 2;
        unsigned km0 = cls0 == 0 ? kh : (cls0 == 1 ? kv : (cls0 == 2 ? k1 : k2));
        unsigned km1 = cls1 == 0 ? kh : (cls1 == 1 ? kv : (cls1 == 2 ? k1 : k2));
        bool wk0 = (km0 & wm)  & 0x1u;
        bool st0 = (km0 & sm_) & 0x1u;
        bool wk1 = ((km1 & wm)  >> 16) & 0x1u;
        bool st1 = ((km1 & sm_) >> 16) & 0x1u;

        unsigned we = __ballot_sync(0xffffffffu, wk0);
        unsigned wo = __ballot_sync(0xffffffffu, wk1);
        unsigned se = __ballot_sync(0xffffffffu, st0);
        unsigned so = __ballot_sync(0xffffffffu, st1);
        if (lane < 4) {
            bool is_st = lane >= 2;
            int hi = lane & 1;
            unsigned e = is_st ? se : we;
            unsigned o = is_st ? so : wo;
            if (hi) { e >>= 16; o >>= 16; }
            unsigned wordv = spread16(e) | (spread16(o) << 1);
            uint32_t* dst = is_st ? (g_strong + obase) : (g_weak + obase);
            dst[(size_t)(r0 + rr) * WPR + 2 * wgrp + hi] = wordv;
        }
    }
}

// ---------------- bitwise hysteresis: 1 CTA/image, 1 row/thread, regs-resident
__global__ __launch_bounds__(512) void k_hyster() {
    extern __shared__ uint32_t sbuf[];   // 2 buffers of [512][HPITCH]
    const int t = threadIdx.x;           // row index 0..511
    const int im = blockIdx.x >> 5, b = blockIdx.x & 31;
    const size_t base = ((size_t)(im * BATCH + b)) * WORDS_PER_IMG + (size_t)t * WPR;

    uint32_t w[WPR], s[WPR], c[WPR];
    {
        const uint4* pw = (const uint4*)(g_weak + base);
        const uint4* ps = (const uint4*)(g_strong + base);
#pragma unroll
        for (int q = 0; q < 4; q++) {
            uint4 a = pw[q];
            w[4*q+0]=a.x; w[4*q+1]=a.y; w[4*q+2]=a.z; w[4*q+3]=a.w;
            uint4 d = ps[q];
            s[4*q+0]=d.x; s[4*q+1]=d.y; s[4*q+2]=d.z; s[4*q+3]=d.w;
        }
    }
#pragma unroll
    for (int i = 0; i < WPR; i++) c[i] = s[i];

    uint32_t* b0 = sbuf;
    uint32_t* b1 = sbuf + HH * HPITCH;
#pragma unroll
    for (int i = 0; i < WPR; i++) b0[t * HPITCH + i] = c[i];
    __syncthreads();

    for (int it = 0; it < 64; ++it) {
        const uint32_t* rd = (it & 1) ? b1 : b0;
        uint32_t*       wr = (it & 1) ? b0 : b1;
        const uint32_t* pu = rd + (t - 1) * HPITCH;
        const uint32_t* pd = rd + (t + 1) * HPITCH;
        uint32_t vor[WPR];
#pragma unroll
        for (int i = 0; i < WPR; i++) {
            uint32_t u = (t > 0)      ? pu[i] : 0u;
            uint32_t d = (t < HH - 1) ? pd[i] : 0u;
            vor[i] = u | d | c[i];               // vertical max (separable)
        }
        uint32_t ch = 0u;
#pragma unroll
        for (int i = 0; i < WPR; i++) {
            uint32_t lo = (i > 0)       ? vor[i - 1] : 0u;
            uint32_t hi = (i < WPR - 1) ? vor[i + 1] : 0u;
            uint32_t l = __funnelshift_l(lo, vor[i], 1);   // col-1 values
            uint32_t r = __funnelshift_r(vor[i], hi, 1);   // col+1 values
            uint32_t d3 = l | vor[i] | r;                  // 3x3 dilate done
            uint32_t nv = (d3 & w[i]) | s[i];
            ch |= nv ^ c[i];
            c[i] = nv;
            wr[t * HPITCH + i] = nv;
        }
        int any = __syncthreads_or((int)(ch != 0u));
        if (!any) break;  // fixed point => identical to reference while_loop
    }

    {
        uint4* pe = (uint4*)(g_edges + base);
#pragma unroll
        for (int q = 0; q < 4; q++)
            pe[q] = make_uint4(c[4*q+0], c[4*q+1], c[4*q+2], c[4*q+3]);
    }
}

// ---------------- XOR popcount reduction + sqrt + output -------------------
__global__ __launch_bounds__(256) void k_diff(float* out, int n) {
    const int totalv = (BATCH * WORDS_PER_IMG) / 4;    // uint4 per image-set
    const uint4* ea = (const uint4*)g_edges;
    const uint4* eb = ea + totalv;
    int idx = blockIdx.x * blockDim.x + threadIdx.x;
    int sum = 0;
    for (int i = idx; i < totalv; i += gridDim.x * blockDim.x) {
        uint4 a = ea[i], d = eb[i];
        sum += __popc(a.x ^ d.x) + __popc(a.y ^ d.y)
             + __popc(a.z ^ d.z) + __popc(a.w ^ d.w);
    }
#pragma unroll
    for (int o = 16; o > 0; o >>= 1) sum += __shfl_down_sync(0xffffffffu, sum, o);
    __shared__ int wsum[8];
    int lane = threadIdx.x & 31, wq = threadIdx.x >> 5;
    if (lane == 0) wsum[wq] = sum;
    __syncthreads();
    if (threadIdx.x == 0) {
        int s2 = 0;
#pragma unroll
        for (int i = 0; i < 8; i++) s2 += wsum[i];
        atomicAdd(&g_count, (unsigned)s2);
        __threadfence();
        unsigned ticket = atomicAdd(&g_done, 1u);
        if (ticket == gridDim.x - 1) {          // last block: finalize
            unsigned total = atomicAdd(&g_count, 0u);
            float v = sqrtf((float)total);
            for (int i = 0; i < n; i++) out[i] = v;
        }
    }
}

// ---------------- launch ---------------------------------------------------
extern "C" void kernel_launch(void* const* d_in, const int* in_sizes, int n_in,
                              void* d_out, int out_size) {
    const float* A = (const float*)d_in[0];
    const float* B = (const float*)d_in[1];

    size_t smemF = (size_t)(GRAY_ROWS * 256 + MAG_ROWS * MAGP2) * sizeof(__half2)
                 + (size_t)TILE_H * 256;                                      // ~78.3KB
    size_t smemH = (size_t)2 * HH * HPITCH * sizeof(uint32_t);                // 69,632B

    cudaFuncSetAttribute(k_frontend, cudaFuncAttributeMaxDynamicSharedMemorySize, (int)smemF);
    cudaFuncSetAttribute(k_hyster,   cudaFuncAttributeMaxDynamicSharedMemorySize, (int)smemH);

    k_frontend<<<dim3(HH / TILE_H, BATCH, 2), FTHREADS, smemF>>>(A, B);
    k_hyster<<<2 * BATCH, 512, smemH>>>();
    k_diff<<<256, 256>>>((float*)d_out, out_size);
}

// round 8
// speedup vs baseline: 1.2869x; 1.1616x over previous
#include <cuda_runtime.h>
#include <cuda_fp16.h>
#include <cstdint>

#define HH 512
#define WW 512
#define BATCH 32
#define WPR 16                       // uint32 words per row (512 bits)
#define WORDS_PER_IMG (HH * WPR)     // 8192 words = 32KB
#define TILE_H 32
#define GRAY_ROWS (TILE_H + 4)       // 36
#define MAG_ROWS  (TILE_H + 2)       // 34
#define MAGP2 260                    // mag pitch in half2 (2 zero half2 pads each side)
#define HPITCH 17                    // hysteresis exchange pitch (conflict-free)
#define FTHREADS 768

// ---------------- device scratch (no allocations allowed) ----------------
__device__ uint32_t g_weak  [2 * BATCH * WORDS_PER_IMG];
__device__ uint32_t g_strong[2 * BATCH * WORDS_PER_IMG];
__device__ uint32_t g_edges [2 * BATCH * WORDS_PER_IMG];
__device__ unsigned int g_count;
__device__ unsigned int g_done;

__device__ __forceinline__ unsigned spread4(unsigned x) {   // bit i -> bit 4i (8 bits in)
    x &= 0xFFu;
    x = (x | (x << 12)) & 0x000F000Fu;
    x = (x | (x << 6))  & 0x03030303u;
    x = (x | (x << 3))  & 0x11111111u;
    return x;
}

__device__ __forceinline__ __half2 u2h(unsigned u) { return *reinterpret_cast<__half2*>(&u); }
__device__ __forceinline__ unsigned h2u(__half2 h) { return *reinterpret_cast<unsigned*>(&h); }

// pair (X.hi, Y.lo): covers cols (c-1, c) when X = word before Y
__device__ __forceinline__ __half2 prhl(__half2 X, __half2 Y) {
    return __halves2half2(__high2half(X), __low2half(Y));
}

// gray quad: for 4 px (word pair w0=2*c4, w1=2*c4+1), reflect at image edges.
// outputs: L (c-1,c), C0 (c,c+1), R (c+1,c+2) [=L of pair1], C1 (c+2,c+3), R1 (c+3,c+4)
__device__ __forceinline__ void gquad(const __half2* row, int c4,
                                      __half2& L, __half2& C0, __half2& R,
                                      __half2& C1, __half2& R1) {
    uint2 ab = *reinterpret_cast<const uint2*>(&row[2 * c4]);
    __half2 A = u2h(ab.x), B = u2h(ab.y);
    __half2 P = (c4 > 0)   ? row[2 * c4 - 1] : __lowhigh2highlow(A);
    __half2 N = (c4 < 127) ? row[2 * c4 + 2] : __lowhigh2highlow(B);
    L  = (c4 > 0)   ? prhl(P, A) : P;    // reflect: (g1,g0)
    R1 = (c4 < 127) ? prhl(B, N) : N;    // reflect: (g511,g510)
    C0 = A; C1 = B;
    R  = prhl(A, B);
}

// mag quad: zero-padded (2 words each side), branch-free
__device__ __forceinline__ void mquad(const __half2* row, int c4,
                                      __half2& L, __half2& C0, __half2& R,
                                      __half2& C1, __half2& R1) {
    uint2 ab = *reinterpret_cast<const uint2*>(&row[2 * c4 + 2]);
    __half2 A = u2h(ab.x), B = u2h(ab.y);
    __half2 P = row[2 * c4 + 1];
    __half2 N = row[2 * c4 + 4];
    L = prhl(P, A); R = prhl(A, B); R1 = prhl(B, N);
    C0 = A; C1 = B;
}

// Sobel on half2 triples (all values exact integers -> exact in fp16)
__device__ __forceinline__ void sobel2(__half2 tL, __half2 tC, __half2 tR,
                                       __half2 mL, __half2 mR,
                                       __half2 bL, __half2 bC, __half2 bR,
                                       __half2& gx2, __half2& gy2) {
    const __half2 two2 = __floats2half2_rn(2.0f, 2.0f);
    __half2 dt = __hsub2(tR, tL);
    __half2 dm = __hsub2(mR, mL);
    __half2 db = __hsub2(bR, bL);
    gx2 = __hadd2(__hfma2(two2, dm, dt), db);
    __half2 st = __hfma2(two2, tC, __hadd2(tL, tR));
    __half2 sb = __hfma2(two2, bC, __hadd2(bL, bR));
    gy2 = __hsub2(sb, st);
}

__device__ __forceinline__ float grayq(float r, float g, float b) {
    // match XLA: ((0.299*R + 0.587*G) + 0.114*B), each op separately rounded
    float v = __fadd_rn(__fadd_rn(__fmul_rn(0.299f, r), __fmul_rn(0.587f, g)),
                        __fmul_rn(0.114f, b));
    return fminf(fmaxf(floorf(__fmul_rn(v, 255.0f)), 0.0f), 255.0f);
}

// classification for one half2 pair of (gx,gy): 2-bit classes for both px
__device__ __forceinline__ int classify2(__half2 gx2, __half2 gy2) {
    float2 gxf = __half22float2(gx2);
    float2 gyf = __half22float2(gy2);
    float ax0 = fabsf(gxf.x), ay0 = fabsf(gyf.x);
    float ax1 = fabsf(gxf.y), ay1 = fabsf(gyf.y);
    bool h0 = ay0 <= __fmul_rn((float)0.4142135623730951, ax0);
    bool v0 = ay0 >= __fmul_rn((float)2.414213562373095,  ax0);
    bool s0 = __fmul_rn(gxf.x, gyf.x) >= 0.0f;
    bool h1 = ay1 <= __fmul_rn((float)0.4142135623730951, ax1);
    bool v1 = ay1 >= __fmul_rn((float)2.414213562373095,  ax1);
    bool s1 = __fmul_rn(gxf.y, gyf.y) >= 0.0f;
    int cls0 = h0 ? 0 : (v0 ? 1 : (s0 ? 2 : 3));
    int cls1 = h1 ? 0 : (v1 ? 1 : (s1 ? 2 : 3));
    return cls0 | (cls1 << 2);
}

// ---------------- fused gray -> sobel+class -> NMS -> threshold -> bitpack
__global__ __launch_bounds__(FTHREADS, 2) void k_frontend(const float* __restrict__ A,
                                                          const float* __restrict__ B) {
    extern __shared__ __half2 smem2[];
    __half2* sg2 = smem2;                      // [GRAY_ROWS][256]
    __half2* sm2 = smem2 + GRAY_ROWS * 256;    // [MAG_ROWS][MAGP2]
    uint8_t* sdc = (uint8_t*)(smem2 + GRAY_ROWS * 256 + MAG_ROWS * MAGP2); // [TILE_H][128]

    const int tid  = threadIdx.x;
    const int tile = blockIdx.x;
    const int b    = blockIdx.y;
    const int im   = blockIdx.z;
    const int r0   = tile * TILE_H;
    const float* img = (im == 0 ? A : B) + (size_t)b * 3 * HH * WW;

    if (tile == 0 && b == 0 && im == 0 && tid == 0) { g_count = 0u; g_done = 0u; }

    // Stage 1: quantized grayscale, 4 px/thread via float4, reflect rows (halo 2)
    for (int p = tid; p < GRAY_ROWS * 128; p += FTHREADS) {
        int rr = p >> 7, c4 = p & 127;
        int gr = r0 - 2 + rr;
        gr = gr < 0 ? -gr : (gr > HH - 1 ? 2 * (HH - 1) - gr : gr);
        const float4* base = (const float4*)(img + gr * WW) + c4;
        float4 r4 = base[0];
        float4 g4 = base[(HH * WW) / 4];
        float4 b4 = base[(2 * HH * WW) / 4];
        __half2 h01 = __floats2half2_rn(grayq(r4.x, g4.x, b4.x), grayq(r4.y, g4.y, b4.y));
        __half2 h23 = __floats2half2_rn(grayq(r4.z, g4.z, b4.z), grayq(r4.w, g4.w, b4.w));
        uint2 pk; pk.x = h2u(h01); pk.y = h2u(h23);
        *reinterpret_cast<uint2*>(&sg2[rr * 256 + 2 * c4]) = pk;
    }
    __syncthreads();

    // Stage 2: magnitude + direction class, 4 px/thread
    for (int p = tid; p < MAG_ROWS * 128; p += FTHREADS) {
        int rr = p >> 7, c4 = p & 127;
        int gr = r0 - 1 + rr;
        __half2 m20 = __floats2half2_rn(0.0f, 0.0f);
        __half2 m21 = m20;
        if (gr >= 0 && gr < HH) {
            int sr = rr + 1;
            __half2 tL, tC0, tR, tC1, tR1;
            __half2 mL, mC0, mR, mC1, mR1;
            __half2 bL, bC0, bR, bC1, bR1;
            gquad(sg2 + (sr - 1) * 256, c4, tL, tC0, tR, tC1, tR1);
            gquad(sg2 +  sr      * 256, c4, mL, mC0, mR, mC1, mR1);
            gquad(sg2 + (sr + 1) * 256, c4, bL, bC0, bR, bC1, bR1);
            __half2 gx0, gy0, gx1, gy1;
            sobel2(tL, tC0, tR,  mL, mR,  bL, bC0, bR,  gx0, gy0);   // pair0
            sobel2(tR, tC1, tR1, mR, mR1, bR, bC1, bR1, gx1, gy1);   // pair1 (L1=R0)
            m20 = __hadd2(__habs2(gx0), __habs2(gy0));   // <= 2040, exact
            m21 = __hadd2(__habs2(gx1), __habs2(gy1));
            if (rr >= 1 && rr <= TILE_H) {
                int cb = classify2(gx0, gy0) | (classify2(gx1, gy1) << 4);
                sdc[(rr - 1) * 128 + c4] = (uint8_t)cb;
            }
        }
        uint2 pk; pk.x = h2u(m20); pk.y = h2u(m21);
        *reinterpret_cast<uint2*>(&sm2[rr * MAGP2 + 2 * c4 + 2]) = pk;
    }
    {
        uint2 z2; z2.x = 0u; z2.y = 0u;
        for (int r = tid; r < MAG_ROWS; r += FTHREADS) {
            *reinterpret_cast<uint2*>(&sm2[r * MAGP2])       = z2;
            *reinterpret_cast<uint2*>(&sm2[r * MAGP2 + 258]) = z2;
        }
    }
    __syncthreads();

    // Stage 3: NMS from cached mag+class + threshold + bitpack; 4 px/thread
    const int lane = tid & 31;
    const size_t obase = ((size_t)(im * BATCH + b)) * WORDS_PER_IMG;
    const __half2 h25 = __floats2half2_rn(25.0f, 25.0f);
    const __half2 h76 = __floats2half2_rn(76.0f, 76.0f);
    for (int pt = tid; pt < TILE_H * 128; pt += FTHREADS) {
        int rr = pt >> 7, c4 = pt & 127;       // rr uniform per warp

        __half2 tL, tC0, tR, tC1, tR1;
        __half2 mL, mC0, mR, mC1, mR1;
        __half2 bL, bC0, bR, bC1, bR1;
        mquad(sm2 +  rr      * MAGP2, c4, tL, tC0, tR, tC1, tR1);
        mquad(sm2 + (rr + 1) * MAGP2, c4, mL, mC0, mR, mC1, mR1);
        mquad(sm2 + (rr + 2) * MAGP2, c4, bL, bC0, bR, bC1, bR1);

        // pair0 (cols c, c+1)
        unsigned kh0 = __hgt2_mask(mC0, mL)  & __hge2_mask(mC0, mR);
        unsigned kv0 = __hgt2_mask(mC0, tC0) & __hge2_mask(mC0, bC0);
        unsigned k10 = __hgt2_mask(mC0, tL)  & __hge2_mask(mC0, bR);
        unsigned k20 = __hgt2_mask(mC0, tR)  & __hge2_mask(mC0, bL);
        unsigned wm0 = __hgt2_mask(mC0, h25);
        unsigned sm0 = __hgt2_mask(mC0, h76);
        // pair1 (cols c+2, c+3)
        unsigned kh1 = __hgt2_mask(mC1, mR)  & __hge2_mask(mC1, mR1);
        unsigned kv1 = __hgt2_mask(mC1, tC1) & __hge2_mask(mC1, bC1);
        unsigned k11 = __hgt2_mask(mC1, tR)  & __hge2_mask(mC1, bR1);
        unsigned k21 = __hgt2_mask(mC1, tR1) & __hge2_mask(mC1, bR);
        unsigned wm1 = __hgt2_mask(mC1, h25);
        unsigned sm1 = __hgt2_mask(mC1, h76);

        int cb = sdc[rr * 128 + c4];
        int c0 = cb & 3, c1 = (cb >> 2) & 3, c2_ = (cb >> 4) & 3, c3 = (cb >> 6) & 3;
        unsigned s0 = c0 == 0 ? kh0 : (c0 == 1 ? kv0 : (c0 == 2 ? k10 : k20));
        unsigned s1 = c1 == 0 ? kh0 : (c1 == 1 ? kv0 : (c1 == 2 ? k10 : k20));
        unsigned s2 = c2_ == 0 ? kh1 : (c2_ == 1 ? kv1 : (c2_ == 2 ? k11 : k21));
        unsigned s3 = c3 == 0 ? kh1 : (c3 == 1 ? kv1 : (c3 == 2 ? k11 : k21));
        bool wk0 =  (s0 & wm0)         & 1u;
        bool st0 =  (s0 & sm0)         & 1u;
        bool wk1 = ((s1 & wm0) >> 16)  & 1u;
        bool st1 = ((s1 & sm0) >> 16)  & 1u;
        bool wk2 =  (s2 & wm1)         & 1u;
        bool st2 =  (s2 & sm1)         & 1u;
        bool wk3 = ((s3 & wm1) >> 16)  & 1u;
        bool st3 = ((s3 & sm1) >> 16)  & 1u;

        unsigned bw0 = __ballot_sync(0xffffffffu, wk0);
        unsigned bw1 = __ballot_sync(0xffffffffu, wk1);
        unsigned bw2 = __ballot_sync(0xffffffffu, wk2);
        unsigned bw3 = __ballot_sync(0xffffffffu, wk3);
        unsigned bs0 = __ballot_sync(0xffffffffu, st0);
        unsigned bs1 = __ballot_sync(0xffffffffu, st1);
        unsigned bs2 = __ballot_sync(0xffffffffu, st2);
        unsigned bs3 = __ballot_sync(0xffffffffu, st3);

        if (lane < 16) {
            int m = lane & 3;
            bool is_st = lane >= 8;          // lanes 0-3 unused? no: 0-3 weak,8-11 strong
            // use lanes 0-3 (weak) and 8-11 (strong)
            if ((lane & 7) < 4) {
                unsigned x0 = is_st ? bs0 : bw0;
                unsigned x1 = is_st ? bs1 : bw1;
                unsigned x2 = is_st ? bs2 : bw2;
                unsigned x3 = is_st ? bs3 : bw3;
                int sh = 8 * m;
                unsigned wordv = spread4(x0 >> sh) | (spread4(x1 >> sh) << 1)
                               | (spread4(x2 >> sh) << 2) | (spread4(x3 >> sh) << 3);
                uint32_t* dst = is_st ? (g_strong + obase) : (g_weak + obase);
                int wbase = (c4 & ~31) >> 3;           // warp's first word index
                dst[(size_t)(r0 + rr) * WPR + wbase + m] = wordv;
            }
        }
    }
}

// ---------------- bitwise hysteresis: 1 CTA/image, 1 row/thread, regs-resident
__global__ __launch_bounds__(512) void k_hyster() {
    extern __shared__ uint32_t sbuf[];   // 2 buffers of [512][HPITCH]
    const int t = threadIdx.x;           // row index 0..511
    const int im = blockIdx.x >> 5, b = blockIdx.x & 31;
    const size_t base = ((size_t)(im * BATCH + b)) * WORDS_PER_IMG + (size_t)t * WPR;

    uint32_t w[WPR], s[WPR], c[WPR];
    {
        const uint4* pw = (const uint4*)(g_weak + base);
        const uint4* ps = (const uint4*)(g_strong + base);
#pragma unroll
        for (int q = 0; q < 4; q++) {
            uint4 a = pw[q];
            w[4*q+0]=a.x; w[4*q+1]=a.y; w[4*q+2]=a.z; w[4*q+3]=a.w;
            uint4 d = ps[q];
            s[4*q+0]=d.x; s[4*q+1]=d.y; s[4*q+2]=d.z; s[4*q+3]=d.w;
        }
    }
#pragma unroll
    for (int i = 0; i < WPR; i++) c[i] = s[i];

    uint32_t* b0 = sbuf;
    uint32_t* b1 = sbuf + HH * HPITCH;
#pragma unroll
    for (int i = 0; i < WPR; i++) b0[t * HPITCH + i] = c[i];
    __syncthreads();

    for (int it = 0; it < 64; ++it) {
        const uint32_t* rd = (it & 1) ? b1 : b0;
        uint32_t*       wr = (it & 1) ? b0 : b1;
        const uint32_t* pu = rd + (t - 1) * HPITCH;
        const uint32_t* pd = rd + (t + 1) * HPITCH;
        uint32_t vor[WPR];
#pragma unroll
        for (int i = 0; i < WPR; i++) {
            uint32_t u = (t > 0)      ? pu[i] : 0u;
            uint32_t d = (t < HH - 1) ? pd[i] : 0u;
            vor[i] = u | d | c[i];               // vertical max (separable)
        }
        uint32_t ch = 0u;
#pragma unroll
        for (int i = 0; i < WPR; i++) {
            uint32_t lo = (i > 0)       ? vor[i - 1] : 0u;
            uint32_t hi = (i < WPR - 1) ? vor[i + 1] : 0u;
            uint32_t l = __funnelshift_l(lo, vor[i], 1);   // col-1 values
            uint32_t r = __funnelshift_r(vor[i], hi, 1);   // col+1 values
            uint32_t d3 = l | vor[i] | r;                  // 3x3 dilate done
            uint32_t nv = (d3 & w[i]) | s[i];
            ch |= nv ^ c[i];
            c[i] = nv;
            wr[t * HPITCH + i] = nv;
        }
        int any = __syncthreads_or((int)(ch != 0u));
        if (!any) break;  // fixed point => identical to reference while_loop
    }

    {
        uint4* pe = (uint4*)(g_edges + base);
#pragma unroll
        for (int q = 0; q < 4; q++)
            pe[q] = make_uint4(c[4*q+0], c[4*q+1], c[4*q+2], c[4*q+3]);
    }
}

// ---------------- XOR popcount reduction + sqrt + output -------------------
__global__ __launch_bounds__(256) void k_diff(float* out, int n) {
    const int totalv = (BATCH * WORDS_PER_IMG) / 4;    // uint4 per image-set
    const uint4* ea = (const uint4*)g_edges;
    const uint4* eb = ea + totalv;
    int idx = blockIdx.x * blockDim.x + threadIdx.x;
    int sum = 0;
    for (int i = idx; i < totalv; i += gridDim.x * blockDim.x) {
        uint4 a = ea[i], d = eb[i];
        sum += __popc(a.x ^ d.x) + __popc(a.y ^ d.y)
             + __popc(a.z ^ d.z) + __popc(a.w ^ d.w);
    }
#pragma unroll
    for (int o = 16; o > 0; o >>= 1) sum += __shfl_down_sync(0xffffffffu, sum, o);
    __shared__ int wsum[8];
    int lane = threadIdx.x & 31, wq = threadIdx.x >> 5;
    if (lane == 0) wsum[wq] = sum;
    __syncthreads();
    if (threadIdx.x == 0) {
        int s2 = 0;
#pragma unroll
        for (int i = 0; i < 8; i++) s2 += wsum[i];
        atomicAdd(&g_count, (unsigned)s2);
        __threadfence();
        unsigned ticket = atomicAdd(&g_done, 1u);
        if (ticket == gridDim.x - 1) {          // last block: finalize
            unsigned total = atomicAdd(&g_count, 0u);
            float v = sqrtf((float)total);
            for (int i = 0; i < n; i++) out[i] = v;
        }
    }
}

// ---------------- launch ---------------------------------------------------
extern "C" void kernel_launch(void* const* d_in, const int* in_sizes, int n_in,
                              void* d_out, int out_size) {
    const float* A = (const float*)d_in[0];
    const float* B = (const float*)d_in[1];

    size_t smemF = (size_t)(GRAY_ROWS * 256 + MAG_ROWS * MAGP2) * sizeof(__half2)
                 + (size_t)TILE_H * 128;                                      // ~74.6KB
    size_t smemH = (size_t)2 * HH * HPITCH * sizeof(uint32_t);                // 69,632B

    cudaFuncSetAttribute(k_frontend, cudaFuncAttributeMaxDynamicSharedMemorySize, (int)smemF);
    cudaFuncSetAttribute(k_hyster,   cudaFuncAttributeMaxDynamicSharedMemorySize, (int)smemH);

    k_frontend<<<dim3(HH / TILE_H, BATCH, 2), FTHREADS, smemF>>>(A, B);
    k_hyster<<<2 * BATCH, 512, smemH>>>();
    k_diff<<<256, 256>>>((float*)d_out, out_size);
}